// round 14
// baseline (speedup 1.0000x reference)
#include <cuda_runtime.h>
#include <cuda_bf16.h>
#include <cstdint>

// SW128 blocked-atom layout (atom = 8 rows x 64 bf16 = 1024B):
// byte(r,k) = (k>>6)*ACS + (r>>3)*1024 + (r&7)*128 + (((k&63)*2) ^ ((r&7)<<4))
static constexpr int ACS_X = 14336;   // X: 112 rows
static constexpr int ACS_W = 32768;   // W: 256 rows

__device__ __align__(16) __nv_bfloat16 g_Eh[100000 * 128];  // E_hist bf16 natural
__device__ __align__(16) __nv_bfloat16 g_Er[1000 * 128];    // E_reg  bf16 natural
__device__ __align__(16) __nv_bfloat16 g_Wsw[256 * 256];    // W1 bf16 SW128-swizzled

__global__ void convert_kernel(const float* __restrict__ Eh, const float* __restrict__ Er,
                               const float* __restrict__ W1, int nEh2, int nEr2) {
    int i = blockIdx.x * blockDim.x + threadIdx.x;
    if (i < nEh2) {
        float2 v = ((const float2*)Eh)[i];
        ((__nv_bfloat162*)g_Eh)[i] = __floats2bfloat162_rn(v.x, v.y);
    } else if (i < nEh2 + nEr2) {
        int j = i - nEh2;
        float2 v = ((const float2*)Er)[j];
        ((__nv_bfloat162*)g_Er)[j] = __floats2bfloat162_rn(v.x, v.y);
    } else if (i < nEh2 + nEr2 + 65536) {
        int j = i - nEh2 - nEr2;
        int n = j >> 8, k = j & 255;
        uint32_t byte = (uint32_t)(k >> 6) * ACS_W + (uint32_t)(n >> 3) * 1024u
                      + (uint32_t)(n & 7) * 128u
                      + ((((uint32_t)(k & 63)) * 2u) ^ ((uint32_t)(n & 7) << 4));
        g_Wsw[byte >> 1] = __float2bfloat16(W1[n * 256 + k]);
    }
}

// smem: W 131072 | X 57344 | idxH 8192 | idxR 8192 | Tv 512 | floats
static constexpr int SM_X  = 131072;
static constexpr int SM_IH = 188416;
static constexpr int SM_IR = 196608;
static constexpr int SM_TV = 204800;
static constexpr int SM_FL = 205312;
static constexpr int NFL   = 1840;
static constexpr int SMEM_BYTES = SM_FL + NFL * 4;   // 212672

__device__ __forceinline__ uint32_t smem_u32(const void* p) {
    return (uint32_t)__cvta_generic_to_shared(p);
}
__device__ __forceinline__ void cpa16(uint32_t dst, const void* src) {
    asm volatile("cp.async.ca.shared.global [%0], [%1], 16;" :: "r"(dst), "l"(src));
}
#define CPA_COMMIT() asm volatile("cp.async.commit_group;" ::: "memory")
#define CPA_WAIT0()  asm volatile("cp.async.wait_group 0;" ::: "memory")
#define BAR_MW3()    asm volatile("bar.sync 2, 128;" ::: "memory")

__device__ __forceinline__ void ldsm4(uint32_t addr, uint32_t r[4]) {
    asm volatile("ldmatrix.sync.aligned.m8n8.x4.shared.b16 {%0,%1,%2,%3}, [%4];"
                 : "=r"(r[0]), "=r"(r[1]), "=r"(r[2]), "=r"(r[3]) : "r"(addr));
}
__device__ __forceinline__ uint32_t bmul2(uint32_t a, uint32_t t) {
    __nv_bfloat162 x = *reinterpret_cast<__nv_bfloat162*>(&a);
    __nv_bfloat162 y = *reinterpret_cast<__nv_bfloat162*>(&t);
    __nv_bfloat162 r = __hmul2(x, y);
    return *reinterpret_cast<uint32_t*>(&r);
}
__device__ __forceinline__ void mma_bf16(float c[4], const uint32_t a[4], uint32_t b0, uint32_t b1) {
    asm volatile(
        "mma.sync.aligned.m16n8k16.row.col.f32.bf16.bf16.f32 "
        "{%0,%1,%2,%3}, {%4,%5,%6,%7}, {%8,%9}, {%0,%1,%2,%3};\n"
        : "+f"(c[0]), "+f"(c[1]), "+f"(c[2]), "+f"(c[3])
        : "r"(a[0]), "r"(a[1]), "r"(a[2]), "r"(a[3]), "r"(b0), "r"(b1));
}
__device__ __forceinline__ float dot8(uint4 xv, uint4 tv) {
    float s = 0.f;
    const uint32_t* xw = (const uint32_t*)&xv;
    const uint32_t* tw = (const uint32_t*)&tv;
    #pragma unroll
    for (int i = 0; i < 4; ++i) {
        float2 xf = __bfloat1622float2(*reinterpret_cast<const __nv_bfloat162*>(&xw[i]));
        float2 tf = __bfloat1622float2(*reinterpret_cast<const __nv_bfloat162*>(&tw[i]));
        s += xf.x * tf.x + xf.y * tf.y;
    }
    return s;
}

__global__ __launch_bounds__(512, 1)
void nais_kernel(const int* __restrict__ history,
                 const int* __restrict__ target,
                 const int* __restrict__ hregion,
                 const int* __restrict__ tregion,
                 const float* __restrict__ tdist,
                 const float* __restrict__ E_tgt,
                 const float* __restrict__ E_dist,
                 const float* __restrict__ b1,
                 const float* __restrict__ w2,
                 float* __restrict__ out,
                 int B, int H, int G)
{
    extern __shared__ unsigned char smem[];
    unsigned char* Wsc = smem;                 // SW128 W [256 x 256 bf16]
    unsigned char* Xsc = smem + SM_X;          // SW128 X [112 x 256 bf16] raw embeddings
    int* idxH = (int*)(smem + SM_IH);          // [16][128]
    int* idxR = (int*)(smem + SM_IR);
    uint32_t* Tv32 = (uint32_t*)(smem + SM_TV);// 128 words: tvec bf16 natural
    float* fl    = (float*)(smem + SM_FL);
    float* b1s   = fl;            // 256
    float* w2s   = fl + 256;      // 256
    float* sxB   = fl + 512;      // 2 x 128
    float* sppB  = fl + 768;      // 2 x 512
    float* redS  = fl + 1792;     // 16
    float* miscF = fl + 1808;     // 1

    const int tid  = threadIdx.x;
    const int wid  = tid >> 5;
    const int lane = tid & 31;

    const int bbase = blockIdx.x * G;
    if (bbase >= B) return;
    const int gcnt = min(G, B - bbase);

    const uint32_t xs32 = smem_u32(Xsc);

    auto issue_row = [&](int r, int item, int rg) {
        uint32_t gc = (uint32_t)lane;
        uint32_t dst = xs32 + (gc >> 3) * (uint32_t)ACS_X + (uint32_t)(r >> 3) * 1024u
                     + (uint32_t)(r & 7) * 128u + (((gc & 7) * 16u) ^ ((uint32_t)(r & 7) << 4));
        const char* src = (lane < 16)
            ? (const char*)g_Eh + (size_t)item * 256 + lane * 16
            : (const char*)g_Er + (size_t)rg * 256 + (lane - 16) * 16;
        cpa16(dst, src);
    };
    auto build_tvec = [&](int nb, int t) {
        ((__nv_bfloat16*)Tv32)[t] = __float2bfloat16(E_tgt[(size_t)target[nb] * 128 + t]);
        if (t < 64)
            Tv32[64 + t] = ((const uint32_t*)(g_Er + (size_t)tregion[nb] * 128))[t];
    };
    // exp/normalize/out for batch pb (phase parity pp) — warps 12..15 only
    auto do_exp = [&](int pb, int pp, int gi_loc) {
        const int q = wid - 12;                  // 0..3
        const int h = q * 32 + lane;             // 0..127
        float eS = 0.f, eP = 0.f;
        if (h < H) {
            const float* sp = sppB + pp * 512;
            float sc = sp[h] + sp[128 + h] + sp[256 + h] + sp[384 + h]
                     + tdist[pb] * miscF[0];
            float e = __expf(sc);
            if (idxH[gi_loc * 128 + h] == target[pb]) e = 0.f;
            eS = e; eP = e * sxB[pp * 128 + h];
        }
        #pragma unroll
        for (int o = 16; o; o >>= 1) {
            eS += __shfl_down_sync(0xffffffffu, eS, o);
            eP += __shfl_down_sync(0xffffffffu, eP, o);
        }
        if (lane == 0) { redS[q] = eS; redS[4 + q] = eP; }
        BAR_MW3();
        if (q == 0 && lane == 0) {
            float S = redS[0] + redS[1] + redS[2] + redS[3];
            float P = redS[4] + redS[5] + redS[6] + redS[7];
            out[pb] = 1.f / (1.f + __expf(-(P / sqrtf(S))));
        }
    };

    // ---------------- prologue ----------------
    {
        const uint4* src = (const uint4*)g_Wsw;
        uint4* dst = (uint4*)Wsc;
        #pragma unroll 4
        for (int i = tid; i < 131072 / 16; i += 512) dst[i] = src[i];
        for (int i = tid; i < gcnt * H; i += 512) {
            int gi = i / H, h = i - gi * H;
            idxH[gi * 128 + h] = history[(size_t)bbase * H + i];
            idxR[gi * 128 + h] = hregion[(size_t)bbase * H + i];
        }
        if (tid < 256) { b1s[tid] = b1[tid]; w2s[tid] = w2[tid]; }
        for (int i = tid; i < (112 - H) * 32; i += 512) {
            int r = H + (i >> 5);
            uint32_t gc = (uint32_t)(i & 31);
            uint32_t o = (gc >> 3) * (uint32_t)ACS_X + (uint32_t)(r >> 3) * 1024u
                       + (uint32_t)(r & 7) * 128u + (((gc & 7) * 16u) ^ ((uint32_t)(r & 7) << 4));
            *(uint4*)(Xsc + o) = make_uint4(0, 0, 0, 0);
        }
        if (wid == 0) {
            float v = E_dist[lane] + E_dist[lane + 32] + E_dist[lane + 64] + E_dist[lane + 96];
            #pragma unroll
            for (int o = 16; o; o >>= 1) v += __shfl_down_sync(0xffffffffu, v, o);
            if (lane == 0) miscF[0] = v;
        }
        if (tid < 128) build_tvec(bbase, tid);
    }
    __syncthreads();
    for (int h = wid; h < H; h += 16) issue_row(h, idxH[h], idxR[h]);
    CPA_COMMIT(); CPA_WAIT0();
    __syncthreads();

    const int mw = wid >> 2;
    const int nw = wid & 3;
    const int g  = lane >> 2;
    const int tg = lane & 3;
    const int r0 = mw * 32 + g;
    const bool full_m = (mw < 3);

    const int e8  = (lane >> 3) & 1;
    const int e16 = lane >> 4;
    const int l7  = lane & 7;
    const uint32_t baseA = xs32 + (uint32_t)(mw * 4 + e8) * 1024u + (uint32_t)l7 * 128u;
    const uint32_t QA = ((uint32_t)e16 * 16u) ^ ((uint32_t)l7 << 4);
    const uint32_t baseB = smem_u32(Wsc) + (uint32_t)(nw * 8 + e16) * 1024u + (uint32_t)l7 * 128u;
    const uint32_t QB = ((uint32_t)e8 * 16u) ^ ((uint32_t)l7 << 4);

    for (int gi = 0; gi < gcnt; ++gi) {
        const int batch = bbase + gi;
        const int p = gi & 1;

        // ============ phase 1: GEMM + epilogue; mw3 warps also do sx(gi) & exp(gi-1) ============
        {
            float acc[2][8][4];
            #pragma unroll
            for (int mt = 0; mt < 2; ++mt)
                #pragma unroll
                for (int nt = 0; nt < 8; ++nt)
                    #pragma unroll
                    for (int i = 0; i < 4; ++i) acc[mt][nt][i] = 0.f;

            #pragma unroll
            for (int kk = 0; kk < 16; ++kk) {
                const uint32_t kA = (uint32_t)(kk >> 2) * (uint32_t)ACS_X + ((((uint32_t)(kk & 3)) << 5) ^ QA);
                const uint32_t kB = (uint32_t)(kk >> 2) * (uint32_t)ACS_W + ((((uint32_t)(kk & 3)) << 5) ^ QB);
                const uint32_t t_lo = Tv32[kk * 8 + tg];
                const uint32_t t_hi = Tv32[kk * 8 + 4 + tg];
                uint32_t a0[4], a1[4];
                ldsm4(baseA + kA, a0);
                a0[0] = bmul2(a0[0], t_lo); a0[1] = bmul2(a0[1], t_lo);
                a0[2] = bmul2(a0[2], t_hi); a0[3] = bmul2(a0[3], t_hi);
                if (full_m) {
                    ldsm4(baseA + 2048u + kA, a1);
                    a1[0] = bmul2(a1[0], t_lo); a1[1] = bmul2(a1[1], t_lo);
                    a1[2] = bmul2(a1[2], t_hi); a1[3] = bmul2(a1[3], t_hi);
                }
                #pragma unroll
                for (int nt4 = 0; nt4 < 4; ++nt4) {
                    uint32_t b[4];
                    ldsm4(baseB + (uint32_t)nt4 * 2048u + kB, b);
                    mma_bf16(acc[0][2 * nt4],     a0, b[0], b[1]);
                    mma_bf16(acc[0][2 * nt4 + 1], a0, b[2], b[3]);
                    if (full_m) {
                        mma_bf16(acc[1][2 * nt4],     a1, b[0], b[1]);
                        mma_bf16(acc[1][2 * nt4 + 1], a1, b[2], b[3]);
                    }
                }
            }

            // epilogue: +b1, relu, dot w2 -> sppB[p]
            float s0 = 0.f, s1 = 0.f, s2 = 0.f, s3 = 0.f;
            #pragma unroll
            for (int nt = 0; nt < 8; ++nt) {
                int k0 = nw * 64 + nt * 8 + tg * 2;
                float w0 = w2s[k0], w1v = w2s[k0 + 1];
                float q0 = b1s[k0], q1 = b1s[k0 + 1];
                s0 += fmaxf(acc[0][nt][0] + q0, 0.f) * w0 + fmaxf(acc[0][nt][1] + q1, 0.f) * w1v;
                s1 += fmaxf(acc[0][nt][2] + q0, 0.f) * w0 + fmaxf(acc[0][nt][3] + q1, 0.f) * w1v;
                if (full_m) {
                    s2 += fmaxf(acc[1][nt][0] + q0, 0.f) * w0 + fmaxf(acc[1][nt][1] + q1, 0.f) * w1v;
                    s3 += fmaxf(acc[1][nt][2] + q0, 0.f) * w0 + fmaxf(acc[1][nt][3] + q1, 0.f) * w1v;
                }
            }
            s0 += __shfl_xor_sync(0xffffffffu, s0, 1); s0 += __shfl_xor_sync(0xffffffffu, s0, 2);
            s1 += __shfl_xor_sync(0xffffffffu, s1, 1); s1 += __shfl_xor_sync(0xffffffffu, s1, 2);
            if (full_m) {
                s2 += __shfl_xor_sync(0xffffffffu, s2, 1); s2 += __shfl_xor_sync(0xffffffffu, s2, 2);
                s3 += __shfl_xor_sync(0xffffffffu, s3, 1); s3 += __shfl_xor_sync(0xffffffffu, s3, 2);
            }
            if (tg == 0) {
                float* sp = sppB + p * 512 + nw * 128;
                sp[r0]     = s0;
                sp[r0 + 8] = s1;
                if (full_m) { sp[r0 + 16] = s2; sp[r0 + 24] = s3; }
            }

            // ---- mw3 warps: sx(gi) then exp(gi-1)/out(gi-1) in their tensor slack ----
            if (mw == 3) {
                for (int h = (wid - 12); h < H; h += 4) {
                    uint32_t gc = (uint32_t)lane;
                    uint32_t o = (gc >> 3) * (uint32_t)ACS_X + (uint32_t)(h >> 3) * 1024u
                               + (uint32_t)(h & 7) * 128u + (((gc & 7) * 16u) ^ ((uint32_t)(h & 7) << 4));
                    uint4 xv = *(const uint4*)(Xsc + o);
                    uint4 tv = ((const uint4*)Tv32)[lane];
                    float s = dot8(xv, tv);
                    #pragma unroll
                    for (int o2 = 16; o2; o2 >>= 1) s += __shfl_down_sync(0xffffffffu, s, o2);
                    if (lane == 0) sxB[p * 128 + h] = s;
                }
                if (gi > 0) do_exp(batch - 1, p ^ 1, gi - 1);
            }
        }
        __syncthreads();

        // ============ phase 2: cp.async X(gi+1) | tvec(gi+1) | wait ============
        if (gi + 1 < gcnt) {
            const int* ih = idxH + (gi + 1) * 128;
            const int* ir = idxR + (gi + 1) * 128;
            for (int h = wid; h < H; h += 16) issue_row(h, ih[h], ir[h]);
            CPA_COMMIT();
            if (tid < 128) build_tvec(batch + 1, tid);
            CPA_WAIT0();
            __syncthreads();
        }
    }

    // final exp for last batch
    if (wid >= 12) do_exp(bbase + gcnt - 1, (gcnt - 1) & 1, gcnt - 1);
}

extern "C" void kernel_launch(void* const* d_in, const int* in_sizes, int n_in,
                              void* d_out, int out_size)
{
    const int*   history = (const int*)d_in[0];
    const int*   target  = (const int*)d_in[1];
    const int*   hregion = (const int*)d_in[2];
    const int*   tregion = (const int*)d_in[3];
    const float* tdist   = (const float*)d_in[4];
    const float* E_hist  = (const float*)d_in[5];
    const float* E_tgt   = (const float*)d_in[6];
    const float* E_reg   = (const float*)d_in[7];
    const float* E_dist  = (const float*)d_in[8];
    const float* W1      = (const float*)d_in[9];
    const float* b1      = (const float*)d_in[10];
    const float* w2      = (const float*)d_in[11];
    float* out = (float*)d_out;

    const int B = in_sizes[1];                 // target: [B]
    const int H = in_sizes[0] / B;             // history: [B,H]
    const int nEh2 = in_sizes[5] / 2;
    const int nEr2 = in_sizes[7] / 2;

    {
        long total = (long)nEh2 + nEr2 + 65536;
        int blocks = (int)((total + 511) / 512);
        convert_kernel<<<blocks, 512>>>(E_hist, E_reg, W1, nEh2, nEr2);
    }

    const int G = (B + 147) / 148;             // single persistent wave
    const int grid = (B + G - 1) / G;
    cudaFuncSetAttribute(nais_kernel, cudaFuncAttributeMaxDynamicSharedMemorySize, SMEM_BYTES);
    nais_kernel<<<grid, 512, SMEM_BYTES>>>(history, target, hregion, tregion, tdist,
                                           E_tgt, E_dist, b1, w2, out, B, H, G);
}

// round 17
// speedup vs baseline: 2.9509x; 2.9509x over previous
#include <cuda_runtime.h>
#include <cuda_bf16.h>
#include <cstdint>

// SW128 blocked-atom layout (atom = 8 rows x 64 bf16 = 1024B):
// byte(r,k) = (k>>6)*ACS + (r>>3)*1024 + (r&7)*128 + (((k&63)*2) ^ ((r&7)<<4))
static constexpr int ACS_X = 14336;   // X: 112 rows
static constexpr int ACS_W = 32768;   // W: 256 rows

__device__ __align__(16) __nv_bfloat16 g_Eh[100000 * 128];  // E_hist bf16 natural
__device__ __align__(16) __nv_bfloat16 g_Er[1000 * 128];    // E_reg  bf16 natural
__device__ __align__(16) __nv_bfloat16 g_Wsw[256 * 256];    // W1 bf16 SW128-swizzled

// vectorized: thread i handles 4 floats -> 8B bf16 store
__global__ void convert_kernel(const float* __restrict__ Eh, const float* __restrict__ Er,
                               const float* __restrict__ W1, int nEh4, int nEr4) {
    int i = blockIdx.x * blockDim.x + threadIdx.x;
    if (i < nEh4) {
        float4 v = ((const float4*)Eh)[i];
        __nv_bfloat162 lo = __floats2bfloat162_rn(v.x, v.y);
        __nv_bfloat162 hi = __floats2bfloat162_rn(v.z, v.w);
        uint2 o;
        o.x = *reinterpret_cast<uint32_t*>(&lo);
        o.y = *reinterpret_cast<uint32_t*>(&hi);
        ((uint2*)g_Eh)[i] = o;
    } else if (i < nEh4 + nEr4) {
        int j = i - nEh4;
        float4 v = ((const float4*)Er)[j];
        __nv_bfloat162 lo = __floats2bfloat162_rn(v.x, v.y);
        __nv_bfloat162 hi = __floats2bfloat162_rn(v.z, v.w);
        uint2 o;
        o.x = *reinterpret_cast<uint32_t*>(&lo);
        o.y = *reinterpret_cast<uint32_t*>(&hi);
        ((uint2*)g_Er)[j] = o;
    } else if (i < nEh4 + nEr4 + 65536) {
        // W1: scalar scatter into SW128 (only 64K elems; cheap)
        int j = i - nEh4 - nEr4;
        int n = j >> 8, k = j & 255;
        uint32_t byte = (uint32_t)(k >> 6) * ACS_W + (uint32_t)(n >> 3) * 1024u
                      + (uint32_t)(n & 7) * 128u
                      + ((((uint32_t)(k & 63)) * 2u) ^ ((uint32_t)(n & 7) << 4));
        g_Wsw[byte >> 1] = __float2bfloat16(W1[n * 256 + k]);
    }
}

// smem: W 131072 | X 57344 | idxH 8192 | idxR 8192 | Tv 512 | floats
static constexpr int SM_X  = 131072;
static constexpr int SM_IH = 188416;
static constexpr int SM_IR = 196608;
static constexpr int SM_TV = 204800;
static constexpr int SM_FL = 205312;
static constexpr int NFL   = 1248;
static constexpr int SMEM_BYTES = SM_FL + NFL * 4;   // 210304

__device__ __forceinline__ uint32_t smem_u32(const void* p) {
    return (uint32_t)__cvta_generic_to_shared(p);
}
__device__ __forceinline__ void cpa16(uint32_t dst, const void* src) {
    asm volatile("cp.async.ca.shared.global [%0], [%1], 16;" :: "r"(dst), "l"(src));
}
#define CPA_COMMIT() asm volatile("cp.async.commit_group;" ::: "memory")
#define CPA_WAIT0()  asm volatile("cp.async.wait_group 0;" ::: "memory")

__device__ __forceinline__ void ldsm4(uint32_t addr, uint32_t r[4]) {
    asm volatile("ldmatrix.sync.aligned.m8n8.x4.shared.b16 {%0,%1,%2,%3}, [%4];"
                 : "=r"(r[0]), "=r"(r[1]), "=r"(r[2]), "=r"(r[3]) : "r"(addr));
}
__device__ __forceinline__ uint32_t bmul2(uint32_t a, uint32_t t) {
    __nv_bfloat162 x = *reinterpret_cast<__nv_bfloat162*>(&a);
    __nv_bfloat162 y = *reinterpret_cast<__nv_bfloat162*>(&t);
    __nv_bfloat162 r = __hmul2(x, y);
    return *reinterpret_cast<uint32_t*>(&r);
}
__device__ __forceinline__ void mma_bf16(float c[4], const uint32_t a[4], uint32_t b0, uint32_t b1) {
    asm volatile(
        "mma.sync.aligned.m16n8k16.row.col.f32.bf16.bf16.f32 "
        "{%0,%1,%2,%3}, {%4,%5,%6,%7}, {%8,%9}, {%0,%1,%2,%3};\n"
        : "+f"(c[0]), "+f"(c[1]), "+f"(c[2]), "+f"(c[3])
        : "r"(a[0]), "r"(a[1]), "r"(a[2]), "r"(a[3]), "r"(b0), "r"(b1));
}
__device__ __forceinline__ float dot8(uint4 xv, uint4 tv) {
    float s = 0.f;
    const uint32_t* xw = (const uint32_t*)&xv;
    const uint32_t* tw = (const uint32_t*)&tv;
    #pragma unroll
    for (int i = 0; i < 4; ++i) {
        float2 xf = __bfloat1622float2(*reinterpret_cast<const __nv_bfloat162*>(&xw[i]));
        float2 tf = __bfloat1622float2(*reinterpret_cast<const __nv_bfloat162*>(&tw[i]));
        s += xf.x * tf.x + xf.y * tf.y;
    }
    return s;
}

__global__ __launch_bounds__(512, 1)
void nais_kernel(const int* __restrict__ history,
                 const int* __restrict__ target,
                 const int* __restrict__ hregion,
                 const int* __restrict__ tregion,
                 const float* __restrict__ tdist,
                 const float* __restrict__ E_tgt,
                 const float* __restrict__ E_dist,
                 const float* __restrict__ b1,
                 const float* __restrict__ w2,
                 float* __restrict__ out,
                 int B, int H, int G)
{
    extern __shared__ unsigned char smem[];
    unsigned char* Wsc = smem;                 // SW128 W [256 x 256 bf16]
    unsigned char* Xsc = smem + SM_X;          // SW128 X [112 x 256 bf16] raw embeddings
    int* idxH = (int*)(smem + SM_IH);          // [16][128]
    int* idxR = (int*)(smem + SM_IR);
    uint32_t* Tv32 = (uint32_t*)(smem + SM_TV);// 128 words: tvec bf16 natural
    float* fl     = (float*)(smem + SM_FL);
    float* b1s    = fl;            // 256
    float* w2s    = fl + 256;      // 256
    float* sx     = fl + 512;      // 128
    float* spp    = fl + 640;      // 4 x 128
    float* redS   = fl + 1152;     // 16
    float* miscF  = fl + 1168;     // 1 (+pad to 1172)
    float* tdistS = fl + 1172;     // 16
    int*   targS  = (int*)(fl + 1188);   // 16
    int*   tregS  = (int*)(fl + 1204);   // 16

    const int tid  = threadIdx.x;
    const int wid  = tid >> 5;
    const int lane = tid & 31;

    const int bbase = blockIdx.x * G;
    if (bbase >= B) return;
    const int gcnt = min(G, B - bbase);

    const uint32_t xs32 = smem_u32(Xsc);

    auto issue_row = [&](int r, int item, int rg) {
        uint32_t gc = (uint32_t)lane;
        uint32_t dst = xs32 + (gc >> 3) * (uint32_t)ACS_X + (uint32_t)(r >> 3) * 1024u
                     + (uint32_t)(r & 7) * 128u + (((gc & 7) * 16u) ^ ((uint32_t)(r & 7) << 4));
        const char* src = (lane < 16)
            ? (const char*)g_Eh + (size_t)item * 256 + lane * 16
            : (const char*)g_Er + (size_t)rg * 256 + (lane - 16) * 16;
        cpa16(dst, src);
    };
    // build tvec (natural order bf16) from explicit indices; t = 0..127
    auto build_tvec = [&](int tI, int tR, int t) {
        ((__nv_bfloat16*)Tv32)[t] = __float2bfloat16(E_tgt[(size_t)tI * 128 + t]);
        if (t < 64)
            Tv32[64 + t] = ((const uint32_t*)(g_Er + (size_t)tR * 128))[t];
    };

    // ---------------- prologue ----------------
    {
        const uint4* src = (const uint4*)g_Wsw;
        uint4* dst = (uint4*)Wsc;
        #pragma unroll 4
        for (int i = tid; i < 131072 / 16; i += 512) dst[i] = src[i];
        for (int i = tid; i < gcnt * H; i += 512) {
            int gi = i / H, h = i - gi * H;
            idxH[gi * 128 + h] = history[(size_t)bbase * H + i];
            idxR[gi * 128 + h] = hregion[(size_t)bbase * H + i];
        }
        if (tid < 256) { b1s[tid] = b1[tid]; w2s[tid] = w2[tid]; }
        if (tid >= 256 && tid < 256 + 16 && tid - 256 < gcnt) {
            int q = tid - 256;
            tdistS[q] = tdist[bbase + q];
            targS[q]  = target[bbase + q];
            tregS[q]  = tregion[bbase + q];
        }
        for (int i = tid; i < (112 - H) * 32; i += 512) {
            int r = H + (i >> 5);
            uint32_t gc = (uint32_t)(i & 31);
            uint32_t o = (gc >> 3) * (uint32_t)ACS_X + (uint32_t)(r >> 3) * 1024u
                       + (uint32_t)(r & 7) * 128u + (((gc & 7) * 16u) ^ ((uint32_t)(r & 7) << 4));
            *(uint4*)(Xsc + o) = make_uint4(0, 0, 0, 0);
        }
        if (wid == 0) {
            float v = E_dist[lane] + E_dist[lane + 32] + E_dist[lane + 64] + E_dist[lane + 96];
            #pragma unroll
            for (int o = 16; o; o >>= 1) v += __shfl_down_sync(0xffffffffu, v, o);
            if (lane == 0) miscF[0] = v;
        }
        if (tid < 128) build_tvec(target[bbase], tregion[bbase], tid);
    }
    __syncthreads();
    // initial gather: batch 0
    for (int h = wid; h < H; h += 16) issue_row(h, idxH[h], idxR[h]);
    CPA_COMMIT(); CPA_WAIT0();
    __syncthreads();
    const float distsum = miscF[0];

    const int mw = wid >> 2;
    const int nw = wid & 3;
    const int g  = lane >> 2;
    const int tg = lane & 3;
    const int r0 = mw * 32 + g;
    const bool full_m = (mw < 3);

    const int e8  = (lane >> 3) & 1;
    const int e16 = lane >> 4;
    const int l7  = lane & 7;
    const uint32_t baseA = xs32 + (uint32_t)(mw * 4 + e8) * 1024u + (uint32_t)l7 * 128u;
    const uint32_t QA = ((uint32_t)e16 * 16u) ^ ((uint32_t)l7 << 4);
    const uint32_t baseB = smem_u32(Wsc) + (uint32_t)(nw * 8 + e16) * 1024u + (uint32_t)l7 * 128u;
    const uint32_t QB = ((uint32_t)e8 * 16u) ^ ((uint32_t)l7 << 4);

    for (int gi = 0; gi < gcnt; ++gi) {
        const int batch = bbase + gi;

        // ================= phase 1: GEMM (fold tgt via HMUL2) + sx + epilogue =================
        {
            float acc[2][8][4];
            #pragma unroll
            for (int mt = 0; mt < 2; ++mt)
                #pragma unroll
                for (int nt = 0; nt < 8; ++nt)
                    #pragma unroll
                    for (int i = 0; i < 4; ++i) acc[mt][nt][i] = 0.f;

            #pragma unroll
            for (int kk = 0; kk < 16; ++kk) {
                const uint32_t kA = (uint32_t)(kk >> 2) * (uint32_t)ACS_X + ((((uint32_t)(kk & 3)) << 5) ^ QA);
                const uint32_t kB = (uint32_t)(kk >> 2) * (uint32_t)ACS_W + ((((uint32_t)(kk & 3)) << 5) ^ QB);
                const uint32_t t_lo = Tv32[kk * 8 + tg];
                const uint32_t t_hi = Tv32[kk * 8 + 4 + tg];
                uint32_t a0[4], a1[4];
                ldsm4(baseA + kA, a0);
                a0[0] = bmul2(a0[0], t_lo); a0[1] = bmul2(a0[1], t_lo);
                a0[2] = bmul2(a0[2], t_hi); a0[3] = bmul2(a0[3], t_hi);
                if (full_m) {
                    ldsm4(baseA + 2048u + kA, a1);
                    a1[0] = bmul2(a1[0], t_lo); a1[1] = bmul2(a1[1], t_lo);
                    a1[2] = bmul2(a1[2], t_hi); a1[3] = bmul2(a1[3], t_hi);
                }
                #pragma unroll
                for (int nt4 = 0; nt4 < 4; ++nt4) {
                    uint32_t b[4];
                    ldsm4(baseB + (uint32_t)nt4 * 2048u + kB, b);
                    mma_bf16(acc[0][2 * nt4],     a0, b[0], b[1]);
                    mma_bf16(acc[0][2 * nt4 + 1], a0, b[2], b[3]);
                    if (full_m) {
                        mma_bf16(acc[1][2 * nt4],     a1, b[0], b[1]);
                        mma_bf16(acc[1][2 * nt4 + 1], a1, b[2], b[3]);
                    }
                }
            }

            // sx: row h raw-dot tvec (lane = granule) — overlaps tensor drain
            for (int h = wid; h < H; h += 16) {
                uint32_t gc = (uint32_t)lane;
                uint32_t o = (gc >> 3) * (uint32_t)ACS_X + (uint32_t)(h >> 3) * 1024u
                           + (uint32_t)(h & 7) * 128u + (((gc & 7) * 16u) ^ ((uint32_t)(h & 7) << 4));
                uint4 xv = *(const uint4*)(Xsc + o);
                uint4 tv = ((const uint4*)Tv32)[lane];
                float s = dot8(xv, tv);
                #pragma unroll
                for (int o2 = 16; o2; o2 >>= 1) s += __shfl_down_sync(0xffffffffu, s, o2);
                if (lane == 0) sx[h] = s;
            }

            // epilogue: +b1, relu, dot w2
            float s0 = 0.f, s1 = 0.f, s2 = 0.f, s3 = 0.f;
            #pragma unroll
            for (int nt = 0; nt < 8; ++nt) {
                int k0 = nw * 64 + nt * 8 + tg * 2;
                float w0 = w2s[k0], w1v = w2s[k0 + 1];
                float q0 = b1s[k0], q1 = b1s[k0 + 1];
                s0 += fmaxf(acc[0][nt][0] + q0, 0.f) * w0 + fmaxf(acc[0][nt][1] + q1, 0.f) * w1v;
                s1 += fmaxf(acc[0][nt][2] + q0, 0.f) * w0 + fmaxf(acc[0][nt][3] + q1, 0.f) * w1v;
                if (full_m) {
                    s2 += fmaxf(acc[1][nt][0] + q0, 0.f) * w0 + fmaxf(acc[1][nt][1] + q1, 0.f) * w1v;
                    s3 += fmaxf(acc[1][nt][2] + q0, 0.f) * w0 + fmaxf(acc[1][nt][3] + q1, 0.f) * w1v;
                }
            }
            s0 += __shfl_xor_sync(0xffffffffu, s0, 1); s0 += __shfl_xor_sync(0xffffffffu, s0, 2);
            s1 += __shfl_xor_sync(0xffffffffu, s1, 1); s1 += __shfl_xor_sync(0xffffffffu, s1, 2);
            if (full_m) {
                s2 += __shfl_xor_sync(0xffffffffu, s2, 1); s2 += __shfl_xor_sync(0xffffffffu, s2, 2);
                s3 += __shfl_xor_sync(0xffffffffu, s3, 1); s3 += __shfl_xor_sync(0xffffffffu, s3, 2);
            }
            if (tg == 0) {
                float* sp = spp + nw * 128;
                sp[r0]     = s0;
                sp[r0 + 8] = s1;
                if (full_m) { sp[r0 + 16] = s2; sp[r0 + 24] = s3; }
            }
        }
        __syncthreads();

        // ===== phase 2: cp.async X(gi+1) | exp->redS | tvec(gi+1) | wait =====
        if (gi + 1 < gcnt) {
            const int* ih = idxH + (gi + 1) * 128;
            const int* ir = idxR + (gi + 1) * 128;
            for (int h = wid; h < H; h += 16) issue_row(h, ih[h], ir[h]);
        }
        CPA_COMMIT();
        if (tid < 128) {
            float eS = 0.f, eP = 0.f;
            if (tid < H) {
                float sc = spp[tid] + spp[128 + tid] + spp[256 + tid] + spp[384 + tid]
                         + tdistS[gi] * distsum;
                float e = __expf(sc);
                if (idxH[gi * 128 + tid] == targS[gi]) e = 0.f;
                eS = e; eP = e * sx[tid];
            }
            #pragma unroll
            for (int o = 16; o; o >>= 1) {
                eS += __shfl_down_sync(0xffffffffu, eS, o);
                eP += __shfl_down_sync(0xffffffffu, eP, o);
            }
            if (lane == 0) { redS[wid] = eS; redS[8 + wid] = eP; }
        } else if (tid < 256 && gi + 1 < gcnt) {
            build_tvec(targS[gi + 1], tregS[gi + 1], tid - 128);
        }
        CPA_WAIT0();
        __syncthreads();
        if (tid == 0) {
            float S = redS[0] + redS[1] + redS[2] + redS[3];
            float P = redS[8] + redS[9] + redS[10] + redS[11];
            float pred = P * rsqrtf(S);    // attn = exp_A / sum^BETA, BETA=0.5
            out[batch] = 1.f / (1.f + __expf(-pred));
        }
    }
}

extern "C" void kernel_launch(void* const* d_in, const int* in_sizes, int n_in,
                              void* d_out, int out_size)
{
    const int*   history = (const int*)d_in[0];
    const int*   target  = (const int*)d_in[1];
    const int*   hregion = (const int*)d_in[2];
    const int*   tregion = (const int*)d_in[3];
    const float* tdist   = (const float*)d_in[4];
    const float* E_hist  = (const float*)d_in[5];
    const float* E_tgt   = (const float*)d_in[6];
    const float* E_reg   = (const float*)d_in[7];
    const float* E_dist  = (const float*)d_in[8];
    const float* W1      = (const float*)d_in[9];
    const float* b1      = (const float*)d_in[10];
    const float* w2      = (const float*)d_in[11];
    float* out = (float*)d_out;

    const int B = in_sizes[1];                 // target: [B]
    const int H = in_sizes[0] / B;             // history: [B,H]
    const int nEh4 = in_sizes[5] / 4;
    const int nEr4 = in_sizes[7] / 4;

    {
        long total = (long)nEh4 + nEr4 + 65536;
        int blocks = (int)((total + 511) / 512);
        convert_kernel<<<blocks, 512>>>(E_hist, E_reg, W1, nEh4, nEr4);
    }

    const int G = (B + 147) / 148;             // single persistent wave
    const int grid = (B + G - 1) / G;
    cudaFuncSetAttribute(nais_kernel, cudaFuncAttributeMaxDynamicSharedMemorySize, SMEM_BYTES);
    nais_kernel<<<grid, 512, SMEM_BYTES>>>(history, target, hregion, tregion, tdist,
                                           E_tgt, E_dist, b1, w2, out, B, H, G);
}